// round 6
// baseline (speedup 1.0000x reference)
#include <cuda_runtime.h>
#include <math.h>

#define Bk   64
#define Tk   512
#define Dd   96
#define TYk  512
#define Ek   128
#define Pk   2
#define Lk   64
#define HIDk 128

typedef unsigned long long u64;

// ---------------- f32x2 packed math helpers (sm_103a) ----------------------
__device__ __forceinline__ u64 ffma2(u64 a, u64 b, u64 c) {
    u64 d;
    asm("fma.rn.f32x2 %0, %1, %2, %3;" : "=l"(d) : "l"(a), "l"(b), "l"(c));
    return d;
}
__device__ __forceinline__ u64 pack2(float lo, float hi) {
    u64 d; asm("mov.b64 %0, {%1, %2};" : "=l"(d) : "f"(lo), "f"(hi)); return d;
}
__device__ __forceinline__ float2 unpack2(u64 v) {
    float2 r; asm("mov.b64 {%0, %1}, %2;" : "=f"(r.x), "=f"(r.y) : "l"(v)); return r;
}

// Scratch -------------------------------------------------------------------
__device__ float g_coeffs[2][64 * 128];   // per feature-half partial coeffs

// ---------------------------------------------------------------------------
// Kernel 1: attention, feature-split. grid = (2 f-halves, 64 b) x 768 thr.
// ---------------------------------------------------------------------------
__global__ __launch_bounds__(768) void attn_kernel(
    const float* __restrict__ timesteps, const float* __restrict__ X,
    const float* __restrict__ Mm,        const float* __restrict__ te_w,
    const float* __restrict__ te_b,      const float* __restrict__ ow,
    const float* __restrict__ query,     const float* __restrict__ q_w,
    const float* __restrict__ q_b,       const float* __restrict__ k_w,
    const float* __restrict__ k_b,       const float* __restrict__ ob)
{
    __shared__ __align__(16) float s_vt[128][8];
    __shared__ __align__(16) float s_et[512][8];
    __shared__ __align__(16) float s_buf[4][768];
    __shared__ float s_xa[8 * 48];
    __shared__ float s_den[8 * 48];
    __shared__ float s_cl[12][64];
    __shared__ float s_max[8];
    __shared__ float s_c[8];

    int fh = blockIdx.x;
    int b  = blockIdx.y;
    int tid = threadIdx.x;

    float* s_q  = &s_buf[0][0];
    float* s_qp = &s_buf[0][256];
    if (tid < 256) s_q[tid] = query[tid];
    {
        int rg = tid >> 6;
        int l = tid & 63;
        float a = 0.f;
        #pragma unroll 4
        for (int r = rg; r < 192; r += 12) {
            int h = r / 48, jj = r - h * 48;
            a += ow[(h * 192 + 96 + fh * 48 + jj) * 64 + l];
        }
        s_cl[rg][l] = a;
    }
    __syncthreads();
    if (tid < 256) {
        int p = tid >> 7, e = tid & 127;
        float acc = q_b[e];
        #pragma unroll 8
        for (int i = 0; i < 128; ++i)
            acc = fmaf(s_q[p * 128 + i], q_w[i * 128 + e], acc);
        s_qp[tid] = acc;
    }
    __syncthreads();
    for (int idx = tid; idx < 1024; idx += 768) {
        int hp = idx >> 7, ein = idx & 127;
        int h = hp >> 1, p = hp & 1;
        const float4* kr = (const float4*)(k_w + ein * 128 + h * 32);
        const float*  qp = &s_qp[p * 128 + h * 32];
        float acc = 0.f;
        #pragma unroll
        for (int d4 = 0; d4 < 8; ++d4) {
            float4 kv = __ldg(&kr[d4]);
            acc += qp[d4 * 4] * kv.x + qp[d4 * 4 + 1] * kv.y
                 + qp[d4 * 4 + 2] * kv.z + qp[d4 * 4 + 3] * kv.w;
        }
        s_vt[ein][hp] = acc;
    }
    if (tid < 8) {
        int h = tid >> 1, p = tid & 1;
        float acc = 0.f;
        #pragma unroll
        for (int d = 0; d < 32; ++d)
            acc = fmaf(s_qp[p * 128 + h * 32 + d], k_b[h * 32 + d], acc);
        s_c[tid] = acc;
    }
    __syncthreads();

    if (tid < 512) {
        float ts = timesteps[b * Tk + tid];
        u64 acc2[4];
        #pragma unroll
        for (int q = 0; q < 4; ++q) acc2[q] = pack2(s_c[2 * q], s_c[2 * q + 1]);
        const float4* w4p = (const float4*)te_w;
        const float4* b4p = (const float4*)te_b;
        #pragma unroll 4
        for (int e4 = 0; e4 < 32; ++e4) {
            float4 w4 = __ldg(&w4p[e4]);
            float4 b4 = __ldg(&b4p[e4]);
            float em[4];
            em[0] = __sinf(fmaf(ts, w4.x, b4.x));
            em[1] = fmaf(ts, w4.y, b4.y);
            em[2] = fmaf(ts, w4.z, b4.z);
            em[3] = fmaf(ts, w4.w, b4.w);
            #pragma unroll
            for (int j = 0; j < 4; ++j) {
                u64 emd = pack2(em[j], em[j]);
                ulonglong2 va = *(const ulonglong2*)&s_vt[e4 * 4 + j][0];
                ulonglong2 vb = *(const ulonglong2*)&s_vt[e4 * 4 + j][4];
                acc2[0] = ffma2(emd, va.x, acc2[0]);
                acc2[1] = ffma2(emd, va.y, acc2[1]);
                acc2[2] = ffma2(emd, vb.x, acc2[2]);
                acc2[3] = ffma2(emd, vb.y, acc2[3]);
            }
        }
        const float scale = 0.17677669529663687f;
        float2 a0 = unpack2(acc2[0]), a1 = unpack2(acc2[1]);
        float2 a2 = unpack2(acc2[2]), a3 = unpack2(acc2[3]);
        *(float4*)&s_et[tid][0] = make_float4(a0.x * scale, a0.y * scale, a1.x * scale, a1.y * scale);
        *(float4*)&s_et[tid][4] = make_float4(a2.x * scale, a2.y * scale, a3.x * scale, a3.y * scale);
    }
    __syncthreads();

    int warp = tid >> 5, lane = tid & 31;
    if (warp < 8) {
        float m = -1e30f;
        for (int t = lane; t < 512; t += 32) m = fmaxf(m, s_et[t][warp]);
        #pragma unroll
        for (int o = 16; o; o >>= 1) m = fmaxf(m, __shfl_xor_sync(0xffffffffu, m, o));
        if (lane == 0) s_max[warp] = m;
    }
    __syncthreads();
    for (int idx = tid; idx < 8 * 512; idx += 768) {
        int t = idx >> 3, hp = idx & 7;
        s_et[t][hp] = __expf(s_et[t][hp] - s_max[hp]);
    }
    __syncthreads();

    int tsub = tid / 24, f2l = tid - tsub * 24;
    u64 num[2][4], den[2][4];
    #pragma unroll
    for (int fs = 0; fs < 2; ++fs)
        #pragma unroll
        for (int q = 0; q < 4; ++q) { num[fs][q] = 0ull; den[fs][q] = 0ull; }
    {
        const float2* X2 = (const float2*)(X + (size_t)b * Tk * Dd);
        const float2* M2 = (const float2*)(Mm + (size_t)b * Tk * Dd);
        int fb = fh * 24;
        #pragma unroll 4
        for (int q = 0; q < 16; ++q) {
            int t = q * 32 + tsub;
            float2 x2 = __ldg(&X2[t * 48 + fb + f2l]);
            float2 m2 = __ldg(&M2[t * 48 + fb + f2l]);
            ulonglong2 e01 = *(const ulonglong2*)&s_et[t][0];
            ulonglong2 e23 = *(const ulonglong2*)&s_et[t][4];
            u64 m0  = pack2(m2.x, m2.x);
            u64 m1  = pack2(m2.y, m2.y);
            float xma = m2.x * x2.x, xmb = m2.y * x2.y;
            u64 xm0 = pack2(xma, xma);
            u64 xm1 = pack2(xmb, xmb);
            den[0][0] = ffma2(e01.x, m0, den[0][0]);
            den[0][1] = ffma2(e01.y, m0, den[0][1]);
            den[0][2] = ffma2(e23.x, m0, den[0][2]);
            den[0][3] = ffma2(e23.y, m0, den[0][3]);
            num[0][0] = ffma2(e01.x, xm0, num[0][0]);
            num[0][1] = ffma2(e01.y, xm0, num[0][1]);
            num[0][2] = ffma2(e23.x, xm0, num[0][2]);
            num[0][3] = ffma2(e23.y, xm0, num[0][3]);
            den[1][0] = ffma2(e01.x, m1, den[1][0]);
            den[1][1] = ffma2(e01.y, m1, den[1][1]);
            den[1][2] = ffma2(e23.x, m1, den[1][2]);
            den[1][3] = ffma2(e23.y, m1, den[1][3]);
            num[1][0] = ffma2(e01.x, xm1, num[1][0]);
            num[1][1] = ffma2(e01.y, xm1, num[1][1]);
            num[1][2] = ffma2(e23.x, xm1, num[1][2]);
            num[1][3] = ffma2(e23.y, xm1, num[1][3]);
        }
    }
    __syncthreads();

    float r_acc = 0.f;
    #pragma unroll
    for (int g = 0; g < 8; ++g) {
        if ((tsub >> 2) == g) {
            int gl = tsub & 3;
            #pragma unroll
            for (int fs = 0; fs < 2; ++fs) {
                int fl = 2 * f2l + fs;
                #pragma unroll
                for (int qq = 0; qq < 4; ++qq) {
                    float2 vn = unpack2(num[fs][qq]);
                    s_buf[gl][(2 * qq) * 48 + fl]           = vn.x;
                    s_buf[gl][(2 * qq + 1) * 48 + fl]       = vn.y;
                    float2 vd = unpack2(den[fs][qq]);
                    s_buf[gl][384 + (2 * qq) * 48 + fl]     = vd.x;
                    s_buf[gl][384 + (2 * qq + 1) * 48 + fl] = vd.y;
                }
            }
        }
        __syncthreads();
        r_acc += s_buf[0][tid] + s_buf[1][tid] + s_buf[2][tid] + s_buf[3][tid];
        __syncthreads();
    }
    if (tid >= 384) s_den[tid - 384] = r_acc;
    __syncthreads();
    if (tid < 384) s_xa[tid] = r_acc / s_den[tid];
    __syncthreads();

    float* s_scr = (float*)s_et;
    {
        int outIdx = tid & 127;
        int seg = tid >> 7;
        int p = outIdx >> 6, l = outIdx & 63;
        float acc = 0.f;
        #pragma unroll 4
        for (int r = seg * 32; r < seg * 32 + 32; ++r) {
            int h = r / 48, fl = r - h * 48;
            acc = fmaf(s_xa[(h * 2 + p) * 48 + fl],
                       ow[(h * 192 + fh * 48 + fl) * 64 + l], acc);
        }
        s_scr[tid] = acc;
    }
    __syncthreads();
    if (tid < 128) {
        int l = tid & 63;
        float acc = (fh == 0) ? ob[l] : 0.f;
        #pragma unroll
        for (int g = 0; g < 12; ++g) acc += s_cl[g][l];
        #pragma unroll
        for (int seg = 0; seg < 6; ++seg) acc += s_scr[seg * 128 + tid];
        g_coeffs[fh][b * 128 + tid] = acc;
    }
}

// ---------------------------------------------------------------------------
// Kernel 2: event-sweep decoder. One block per batch, 256 threads.
// ---------------------------------------------------------------------------
#define SEG_PITCH 97
#define DYN_SMEM  (2 * 129 * SEG_PITCH * 4)

__global__ __launch_bounds__(256) void decoder_kernel(
    const float* __restrict__ y_ts, const float* __restrict__ w1,
    const float* __restrict__ b1,   const float* __restrict__ w2,
    const float* __restrict__ b2,   float* __restrict__ out)
{
    extern __shared__ float dyn[];
    float* C0 = dyn;                       // [129][SEG_PITCH]
    float* C1 = dyn + 129 * SEG_PITCH;

    __shared__ float sc0[64], sc1[64];
    __shared__ float st[128];
    __shared__ float uA[128], uB[128];
    __shared__ float uiA[128], uiB[128];
    __shared__ float sdA[128], sdB[128];
    __shared__ int   uidx[128], srow[128];

    int b = blockIdx.x;
    int tid = threadIdx.x;

    if (tid < 64) {
        sc0[tid] = g_coeffs[0][b * 128 + tid] + g_coeffs[1][b * 128 + tid];
    } else if (tid < 128) {
        int l = tid - 64;
        sc1[l] = g_coeffs[0][b * 128 + 64 + l] + g_coeffs[1][b * 128 + 64 + l];
    }
    __syncthreads();

    // ---- A_i, B_i and event construction ----
    if (tid < 128) {
        int i = tid;
        float a = b1[i], bb = 0.f;
        #pragma unroll 8
        for (int l = 0; l < 64; ++l) {
            float w = w1[l * 128 + i];
            a  = fmaf(sc0[l], w, a);
            bb = fmaf(sc1[l], w, bb);
        }
        float t, dA, dB;
        bool ini;
        if (bb > 0.f)      { t = -a / bb; dA =  a; dB =  bb; ini = false; }
        else if (bb < 0.f) { t = -a / bb; dA = -a; dB = -bb; ini = true;  }
        else               { t = 3e38f;   dA = 0.f; dB = 0.f; ini = (a > 0.f); }
        st[i] = t; uidx[i] = i;
        uA[i] = dA; uB[i] = dB;
        uiA[i] = ini ? a  : 0.f;
        uiB[i] = ini ? bb : 0.f;
    }
    __syncthreads();

    // ---- bitonic sort of (st, uidx), ascending ----
    for (int k = 2; k <= 128; k <<= 1) {
        for (int j = k >> 1; j > 0; j >>= 1) {
            if (tid < 128) {
                int l = tid ^ j;
                if (l > tid) {
                    bool up = ((tid & k) == 0);
                    float ta = st[tid], tb = st[l];
                    if ((ta > tb) == up) {
                        st[tid] = tb; st[l] = ta;
                        int ia = uidx[tid]; uidx[tid] = uidx[l]; uidx[l] = ia;
                    }
                }
            }
            __syncthreads();
        }
    }
    if (tid < 128) {
        int e = uidx[tid];
        sdA[tid] = uA[e]; sdB[tid] = uB[e]; srow[tid] = e;
    }
    __syncthreads();

    // ---- prefix tables: row 0 = initial active set, row s+1 after event s ----
    if (tid < 96) {
        int j = tid;
        float c0 = 0.f, c1 = 0.f;
        #pragma unroll 4
        for (int i = 0; i < 128; ++i) {
            float w = __ldg(&w2[i * 96 + j]);
            c0 = fmaf(uiA[i], w, c0);
            c1 = fmaf(uiB[i], w, c1);
        }
        C0[j] = c0; C1[j] = c1;
        #pragma unroll 4
        for (int s = 0; s < 128; ++s) {
            float w = __ldg(&w2[srow[s] * 96 + j]);
            c0 = fmaf(sdA[s], w, c0);
            c1 = fmaf(sdB[s], w, c1);
            C0[(s + 1) * SEG_PITCH + j] = c0;
            C1[(s + 1) * SEG_PITCH + j] = c1;
        }
    }
    __syncthreads();

    // ---- eval: thread = (yg 0..31, jg 0..7 -> 12 j) ----
    int yg = tid >> 3, jg = tid & 7;
    int j0 = jg * 12;
    float b2v[12];
    #pragma unroll
    for (int u = 0; u < 12; ++u) b2v[u] = b2[j0 + u];
    const float* yb = y_ts + (size_t)b * TYk;

    #pragma unroll 2
    for (int r = 0; r < 16; ++r) {
        int ty = r * 32 + yg;
        float y = __ldg(&yb[ty]);
        // upper-bound search over 128 sorted thresholds: s = #{t_i <= y} in [0,128]
        int s = 0;
        #pragma unroll
        for (int step = 64; step >= 1; step >>= 1)
            if (st[s + step - 1] <= y) s += step;
        if (st[s > 127 ? 127 : s] <= y && s < 128) ++s;   // 8th probe: allow s == 128
        const float* c0r = &C0[s * SEG_PITCH + j0];
        const float* c1r = &C1[s * SEG_PITCH + j0];
        float* o = out + ((size_t)b * TYk + ty) * Dd + j0;
        #pragma unroll
        for (int u = 0; u < 12; u += 2) {
            float2 ov;
            ov.x = fmaf(y, c1r[u],     c0r[u])     + b2v[u];
            ov.y = fmaf(y, c1r[u + 1], c0r[u + 1]) + b2v[u + 1];
            *(float2*)&o[u] = ov;
        }
    }
}

// ---------------------------------------------------------------------------
extern "C" void kernel_launch(void* const* d_in, const int* in_sizes, int n_in,
                              void* d_out, int out_size)
{
    const float* timesteps = (const float*)d_in[0];
    const float* X         = (const float*)d_in[1];
    const float* Mm        = (const float*)d_in[2];
    const float* y_ts      = (const float*)d_in[3];
    const float* te_w      = (const float*)d_in[4];
    const float* te_b      = (const float*)d_in[5];
    const float* query     = (const float*)d_in[6];
    const float* q_w       = (const float*)d_in[7];
    const float* q_b       = (const float*)d_in[8];
    const float* k_w       = (const float*)d_in[9];
    const float* k_b       = (const float*)d_in[10];
    const float* ow        = (const float*)d_in[11];
    const float* ob        = (const float*)d_in[12];
    const float* w1        = (const float*)d_in[13];
    const float* b1        = (const float*)d_in[14];
    const float* w2        = (const float*)d_in[15];
    const float* b2        = (const float*)d_in[16];
    float* out = (float*)d_out;

    cudaFuncSetAttribute(decoder_kernel,
                         cudaFuncAttributeMaxDynamicSharedMemorySize, DYN_SMEM);

    attn_kernel<<<dim3(2, 64), 768>>>(timesteps, X, Mm, te_w, te_b, ow,
                                      query, q_w, q_b, k_w, k_b, ob);
    decoder_kernel<<<64, 256, DYN_SMEM>>>(y_ts, w1, b1, w2, b2, out);
}

// round 9
// speedup vs baseline: 1.4822x; 1.4822x over previous
#include <cuda_runtime.h>
#include <math.h>

#define Bk   64
#define Tk   512
#define Dd   96
#define TYk  512
#define Ek   128
#define Pk   2
#define Lk   64
#define HIDk 128

typedef unsigned long long u64;

// ---------------- f32x2 packed math helpers (sm_103a) ----------------------
__device__ __forceinline__ u64 ffma2(u64 a, u64 b, u64 c) {
    u64 d;
    asm("fma.rn.f32x2 %0, %1, %2, %3;" : "=l"(d) : "l"(a), "l"(b), "l"(c));
    return d;
}
__device__ __forceinline__ u64 pack2(float lo, float hi) {
    u64 d; asm("mov.b64 %0, {%1, %2};" : "=l"(d) : "f"(lo), "f"(hi)); return d;
}
__device__ __forceinline__ float2 unpack2(u64 v) {
    float2 r; asm("mov.b64 {%0, %1}, %2;" : "=f"(r.x), "=f"(r.y) : "l"(v)); return r;
}

// Scratch -------------------------------------------------------------------
__device__ float g_coeffs[2][64 * 128];   // per feature-half partial coeffs

// ---------------------------------------------------------------------------
// Kernel 1: attention, feature-split. grid = (2 f-halves, 64 b) x 768 thr.
// ---------------------------------------------------------------------------
__global__ __launch_bounds__(768) void attn_kernel(
    const float* __restrict__ timesteps, const float* __restrict__ X,
    const float* __restrict__ Mm,        const float* __restrict__ te_w,
    const float* __restrict__ te_b,      const float* __restrict__ ow,
    const float* __restrict__ query,     const float* __restrict__ q_w,
    const float* __restrict__ q_b,       const float* __restrict__ k_w,
    const float* __restrict__ k_b,       const float* __restrict__ ob)
{
    __shared__ __align__(16) float s_vt[128][8];
    __shared__ __align__(16) float s_et[512][8];
    __shared__ __align__(16) float s_buf[4][768];
    __shared__ float s_xa[8 * 48];
    __shared__ float s_den[8 * 48];
    __shared__ float s_cl[12][64];
    __shared__ float s_max[8];
    __shared__ float s_c[8];

    int fh = blockIdx.x;
    int b  = blockIdx.y;
    int tid = threadIdx.x;

    float* s_q  = &s_buf[0][0];
    float* s_qp = &s_buf[0][256];
    if (tid < 256) s_q[tid] = query[tid];
    {
        int rg = tid >> 6;
        int l = tid & 63;
        float a = 0.f;
        #pragma unroll 4
        for (int r = rg; r < 192; r += 12) {
            int h = r / 48, jj = r - h * 48;
            a += ow[(h * 192 + 96 + fh * 48 + jj) * 64 + l];
        }
        s_cl[rg][l] = a;
    }
    __syncthreads();
    if (tid < 256) {
        int p = tid >> 7, e = tid & 127;
        float acc = q_b[e];
        #pragma unroll 8
        for (int i = 0; i < 128; ++i)
            acc = fmaf(s_q[p * 128 + i], q_w[i * 128 + e], acc);
        s_qp[tid] = acc;
    }
    __syncthreads();
    for (int idx = tid; idx < 1024; idx += 768) {
        int hp = idx >> 7, ein = idx & 127;
        int h = hp >> 1, p = hp & 1;
        const float4* kr = (const float4*)(k_w + ein * 128 + h * 32);
        const float*  qp = &s_qp[p * 128 + h * 32];
        float acc = 0.f;
        #pragma unroll
        for (int d4 = 0; d4 < 8; ++d4) {
            float4 kv = __ldg(&kr[d4]);
            acc += qp[d4 * 4] * kv.x + qp[d4 * 4 + 1] * kv.y
                 + qp[d4 * 4 + 2] * kv.z + qp[d4 * 4 + 3] * kv.w;
        }
        s_vt[ein][hp] = acc;
    }
    if (tid < 8) {
        int h = tid >> 1, p = tid & 1;
        float acc = 0.f;
        #pragma unroll
        for (int d = 0; d < 32; ++d)
            acc = fmaf(s_qp[p * 128 + h * 32 + d], k_b[h * 32 + d], acc);
        s_c[tid] = acc;
    }
    __syncthreads();

    if (tid < 512) {
        float ts = timesteps[b * Tk + tid];
        u64 acc2[4];
        #pragma unroll
        for (int q = 0; q < 4; ++q) acc2[q] = pack2(s_c[2 * q], s_c[2 * q + 1]);
        const float4* w4p = (const float4*)te_w;
        const float4* b4p = (const float4*)te_b;
        #pragma unroll 4
        for (int e4 = 0; e4 < 32; ++e4) {
            float4 w4 = __ldg(&w4p[e4]);
            float4 b4 = __ldg(&b4p[e4]);
            float em[4];
            em[0] = __sinf(fmaf(ts, w4.x, b4.x));
            em[1] = fmaf(ts, w4.y, b4.y);
            em[2] = fmaf(ts, w4.z, b4.z);
            em[3] = fmaf(ts, w4.w, b4.w);
            #pragma unroll
            for (int j = 0; j < 4; ++j) {
                u64 emd = pack2(em[j], em[j]);
                ulonglong2 va = *(const ulonglong2*)&s_vt[e4 * 4 + j][0];
                ulonglong2 vb = *(const ulonglong2*)&s_vt[e4 * 4 + j][4];
                acc2[0] = ffma2(emd, va.x, acc2[0]);
                acc2[1] = ffma2(emd, va.y, acc2[1]);
                acc2[2] = ffma2(emd, vb.x, acc2[2]);
                acc2[3] = ffma2(emd, vb.y, acc2[3]);
            }
        }
        const float scale = 0.17677669529663687f;
        float2 a0 = unpack2(acc2[0]), a1 = unpack2(acc2[1]);
        float2 a2 = unpack2(acc2[2]), a3 = unpack2(acc2[3]);
        *(float4*)&s_et[tid][0] = make_float4(a0.x * scale, a0.y * scale, a1.x * scale, a1.y * scale);
        *(float4*)&s_et[tid][4] = make_float4(a2.x * scale, a2.y * scale, a3.x * scale, a3.y * scale);
    }
    __syncthreads();

    int warp = tid >> 5, lane = tid & 31;
    if (warp < 8) {
        float m = -1e30f;
        for (int t = lane; t < 512; t += 32) m = fmaxf(m, s_et[t][warp]);
        #pragma unroll
        for (int o = 16; o; o >>= 1) m = fmaxf(m, __shfl_xor_sync(0xffffffffu, m, o));
        if (lane == 0) s_max[warp] = m;
    }
    __syncthreads();
    for (int idx = tid; idx < 8 * 512; idx += 768) {
        int t = idx >> 3, hp = idx & 7;
        s_et[t][hp] = __expf(s_et[t][hp] - s_max[hp]);
    }
    __syncthreads();

    int tsub = tid / 24, f2l = tid - tsub * 24;
    u64 num[2][4], den[2][4];
    #pragma unroll
    for (int fs = 0; fs < 2; ++fs)
        #pragma unroll
        for (int q = 0; q < 4; ++q) { num[fs][q] = 0ull; den[fs][q] = 0ull; }
    {
        const float2* X2 = (const float2*)(X + (size_t)b * Tk * Dd);
        const float2* M2 = (const float2*)(Mm + (size_t)b * Tk * Dd);
        int fb = fh * 24;
        #pragma unroll 4
        for (int q = 0; q < 16; ++q) {
            int t = q * 32 + tsub;
            float2 x2 = __ldg(&X2[t * 48 + fb + f2l]);
            float2 m2 = __ldg(&M2[t * 48 + fb + f2l]);
            ulonglong2 e01 = *(const ulonglong2*)&s_et[t][0];
            ulonglong2 e23 = *(const ulonglong2*)&s_et[t][4];
            u64 m0  = pack2(m2.x, m2.x);
            u64 m1  = pack2(m2.y, m2.y);
            float xma = m2.x * x2.x, xmb = m2.y * x2.y;
            u64 xm0 = pack2(xma, xma);
            u64 xm1 = pack2(xmb, xmb);
            den[0][0] = ffma2(e01.x, m0, den[0][0]);
            den[0][1] = ffma2(e01.y, m0, den[0][1]);
            den[0][2] = ffma2(e23.x, m0, den[0][2]);
            den[0][3] = ffma2(e23.y, m0, den[0][3]);
            num[0][0] = ffma2(e01.x, xm0, num[0][0]);
            num[0][1] = ffma2(e01.y, xm0, num[0][1]);
            num[0][2] = ffma2(e23.x, xm0, num[0][2]);
            num[0][3] = ffma2(e23.y, xm0, num[0][3]);
            den[1][0] = ffma2(e01.x, m1, den[1][0]);
            den[1][1] = ffma2(e01.y, m1, den[1][1]);
            den[1][2] = ffma2(e23.x, m1, den[1][2]);
            den[1][3] = ffma2(e23.y, m1, den[1][3]);
            num[1][0] = ffma2(e01.x, xm1, num[1][0]);
            num[1][1] = ffma2(e01.y, xm1, num[1][1]);
            num[1][2] = ffma2(e23.x, xm1, num[1][2]);
            num[1][3] = ffma2(e23.y, xm1, num[1][3]);
        }
    }
    __syncthreads();

    float r_acc = 0.f;
    #pragma unroll
    for (int g = 0; g < 8; ++g) {
        if ((tsub >> 2) == g) {
            int gl = tsub & 3;
            #pragma unroll
            for (int fs = 0; fs < 2; ++fs) {
                int fl = 2 * f2l + fs;
                #pragma unroll
                for (int qq = 0; qq < 4; ++qq) {
                    float2 vn = unpack2(num[fs][qq]);
                    s_buf[gl][(2 * qq) * 48 + fl]           = vn.x;
                    s_buf[gl][(2 * qq + 1) * 48 + fl]       = vn.y;
                    float2 vd = unpack2(den[fs][qq]);
                    s_buf[gl][384 + (2 * qq) * 48 + fl]     = vd.x;
                    s_buf[gl][384 + (2 * qq + 1) * 48 + fl] = vd.y;
                }
            }
        }
        __syncthreads();
        r_acc += s_buf[0][tid] + s_buf[1][tid] + s_buf[2][tid] + s_buf[3][tid];
        __syncthreads();
    }
    if (tid >= 384) s_den[tid - 384] = r_acc;
    __syncthreads();
    if (tid < 384) s_xa[tid] = r_acc / s_den[tid];
    __syncthreads();

    float* s_scr = (float*)s_et;
    {
        int outIdx = tid & 127;
        int seg = tid >> 7;
        int p = outIdx >> 6, l = outIdx & 63;
        float acc = 0.f;
        #pragma unroll 4
        for (int r = seg * 32; r < seg * 32 + 32; ++r) {
            int h = r / 48, fl = r - h * 48;
            acc = fmaf(s_xa[(h * 2 + p) * 48 + fl],
                       ow[(h * 192 + fh * 48 + fl) * 64 + l], acc);
        }
        s_scr[tid] = acc;
    }
    __syncthreads();
    if (tid < 128) {
        int l = tid & 63;
        float acc = (fh == 0) ? ob[l] : 0.f;
        #pragma unroll
        for (int g = 0; g < 12; ++g) acc += s_cl[g][l];
        #pragma unroll
        for (int seg = 0; seg < 6; ++seg) acc += s_scr[seg * 128 + tid];
        g_coeffs[fh][b * 128 + tid] = acc;
    }
}

// ---------------------------------------------------------------------------
// Kernel 2: event-sweep decoder, latency-parallel build. 64 blocks x 512 thr.
//   Dynamic smem layout: w2s (16B-aligned, float4 staging) | C0 | C1 (scalar).
// ---------------------------------------------------------------------------
#define PCH 97
#define DYN_SMEM ((128 * 96 + 2 * 129 * PCH) * 4)

__global__ __launch_bounds__(512) void decoder_kernel(
    const float* __restrict__ y_ts, const float* __restrict__ w1,
    const float* __restrict__ b1,   const float* __restrict__ w2,
    const float* __restrict__ b2,   float* __restrict__ out)
{
    extern __shared__ __align__(16) float dyn[];
    float* w2s = dyn;                      // [128][96]  (offset 0, float4-safe)
    float* C0  = w2s + 128 * 96;           // [129][PCH] (scalar access only)
    float* C1  = C0 + 129 * PCH;

    __shared__ float sc0[64], sc1[64];
    __shared__ float st[128];
    __shared__ float uA[128], uB[128], uiA[128], uiB[128];
    __shared__ float sdA[128], sdB[128];
    __shared__ int   uidx[128], srow[128];
    __shared__ float pA[4][128], pB[4][128];   // split-K partials (reused)
    __shared__ float off0[8][96], off1[8][96];
    __shared__ float sy[512];
    __shared__ int   sseg[512];

    int b = blockIdx.x;
    int tid = threadIdx.x;

    // ---- stage w2 (coalesced float4) + coeffs + y ----
    {
        const float4* src = (const float4*)w2;
        float4* dst = (float4*)w2s;
        #pragma unroll
        for (int i = tid; i < 128 * 96 / 4; i += 512) dst[i] = src[i];
    }
    if (tid < 64) {
        sc0[tid] = g_coeffs[0][b * 128 + tid] + g_coeffs[1][b * 128 + tid];
    } else if (tid < 128) {
        int l = tid - 64;
        sc1[l] = g_coeffs[0][b * 128 + 64 + l] + g_coeffs[1][b * 128 + 64 + l];
    }
    sy[tid] = __ldg(&y_ts[(size_t)b * TYk + tid]);
    __syncthreads();

    // ---- A_i, B_i : 4-way split-K over l ----
    {
        int g = tid >> 7, i = tid & 127;
        float a = 0.f, bb = 0.f;
        #pragma unroll
        for (int l = g * 16; l < g * 16 + 16; ++l) {
            float w = __ldg(&w1[l * 128 + i]);
            a  = fmaf(sc0[l], w, a);
            bb = fmaf(sc1[l], w, bb);
        }
        pA[g][i] = a; pB[g][i] = bb;
    }
    __syncthreads();
    if (tid < 128) {
        int i = tid;
        float a  = b1[i] + pA[0][i] + pA[1][i] + pA[2][i] + pA[3][i];
        float bb = pB[0][i] + pB[1][i] + pB[2][i] + pB[3][i];
        float t, dA, dB;
        bool ini;
        if (bb > 0.f)      { t = -a / bb; dA =  a; dB =  bb; ini = false; }
        else if (bb < 0.f) { t = -a / bb; dA = -a; dB = -bb; ini = true;  }
        else               { t = 3e38f;   dA = 0.f; dB = 0.f; ini = (a > 0.f); }
        st[i] = t; uidx[i] = i;
        uA[i] = dA; uB[i] = dB;
        uiA[i] = ini ? a  : 0.f;
        uiB[i] = ini ? bb : 0.f;
    }
    __syncthreads();

    // ---- bitonic sort of (st, uidx), ascending ----
    for (int k = 2; k <= 128; k <<= 1) {
        for (int j = k >> 1; j > 0; j >>= 1) {
            if (tid < 128) {
                int l = tid ^ j;
                if (l > tid) {
                    bool up = ((tid & k) == 0);
                    float ta = st[tid], tb = st[l];
                    if ((ta > tb) == up) {
                        st[tid] = tb; st[l] = ta;
                        int ia = uidx[tid]; uidx[tid] = uidx[l]; uidx[l] = ia;
                    }
                }
            }
            __syncthreads();
        }
    }
    if (tid < 128) {
        int e = uidx[tid];
        sdA[tid] = uA[e]; sdB[tid] = uB[e]; srow[tid] = e;
    }
    __syncthreads();

    // ---- chunk-local scans: task (c 0..7, j 0..95) ----
    for (int task = tid; task < 768; task += 512) {
        int c = task / 96, j = task - (task / 96) * 96;
        float l0 = 0.f, l1 = 0.f;
        #pragma unroll
        for (int s = 0; s < 16; ++s) {
            int gs = c * 16 + s;
            float w = w2s[srow[gs] * 96 + j];
            l0 = fmaf(sdA[gs], w, l0);
            l1 = fmaf(sdB[gs], w, l1);
            C0[(gs + 1) * PCH + j] = l0;
            C1[(gs + 1) * PCH + j] = l1;
        }
    }
    // ---- init row partials (4-way split over i) ----
    if (tid < 384) {
        int g = tid / 96, j = tid - g * 96;
        float c0 = 0.f, c1 = 0.f;
        #pragma unroll 8
        for (int i = g * 32; i < g * 32 + 32; ++i) {
            float w = w2s[i * 96 + j];
            c0 = fmaf(uiA[i], w, c0);
            c1 = fmaf(uiB[i], w, c1);
        }
        pA[g][j] = c0; pB[g][j] = c1;
    }
    // ---- segment index per ty ----
    {
        float y = sy[tid];
        int s = 0;
        #pragma unroll
        for (int step = 64; step >= 1; step >>= 1)
            if (st[s + step - 1] <= y) s += step;
        if (s < 128 && st[s] <= y) ++s;
        sseg[tid] = s;
    }
    __syncthreads();

    // ---- chunk offsets: off[c][j] = init[j] + sum_{c'<c} chunk_end[c'] ----
    for (int task = tid; task < 768; task += 512) {
        int c = task / 96, j = task - (task / 96) * 96;
        float o0 = pA[0][j] + pA[1][j] + pA[2][j] + pA[3][j];
        float o1 = pB[0][j] + pB[1][j] + pB[2][j] + pB[3][j];
        #pragma unroll 2
        for (int cc = 0; cc < c; ++cc) {
            o0 += C0[(cc * 16 + 16) * PCH + j];
            o1 += C1[(cc * 16 + 16) * PCH + j];
        }
        off0[c][j] = o0; off1[c][j] = o1;
    }
    if (tid < 96) {
        C0[tid] = pA[0][tid] + pA[1][tid] + pA[2][tid] + pA[3][tid];
        C1[tid] = pB[0][tid] + pB[1][tid] + pB[2][tid] + pB[3][tid];
    }
    __syncthreads();
    // ---- apply offsets to rows 1..128 ----
    for (int idx = tid; idx < 128 * 96; idx += 512) {
        int row = (idx / 96) + 1, j = idx - (idx / 96) * 96;
        int c = (row - 1) >> 4;
        C0[row * PCH + j] += off0[c][j];
        C1[row * PCH + j] += off1[c][j];
    }
    __syncthreads();

    // ---- eval: thread = (yg 0..63, jg 0..7 -> 12 j), 8 rounds ----
    int yg = tid >> 3, jg = tid & 7;
    int j0 = jg * 12;
    float b2v[12];
    #pragma unroll
    for (int u = 0; u < 12; ++u) b2v[u] = b2[j0 + u];

    #pragma unroll 2
    for (int r = 0; r < 8; ++r) {
        int ty = r * 64 + yg;
        float y = sy[ty];
        int s = sseg[ty];
        const float* c0r = &C0[s * PCH + j0];
        const float* c1r = &C1[s * PCH + j0];
        float* o = out + ((size_t)b * TYk + ty) * Dd + j0;
        #pragma unroll
        for (int u = 0; u < 12; u += 2) {
            float2 ov;
            ov.x = fmaf(y, c1r[u],     c0r[u])     + b2v[u];
            ov.y = fmaf(y, c1r[u + 1], c0r[u + 1]) + b2v[u + 1];
            *(float2*)&o[u] = ov;
        }
    }
}

// ---------------------------------------------------------------------------
extern "C" void kernel_launch(void* const* d_in, const int* in_sizes, int n_in,
                              void* d_out, int out_size)
{
    const float* timesteps = (const float*)d_in[0];
    const float* X         = (const float*)d_in[1];
    const float* Mm        = (const float*)d_in[2];
    const float* y_ts      = (const float*)d_in[3];
    const float* te_w      = (const float*)d_in[4];
    const float* te_b      = (const float*)d_in[5];
    const float* query     = (const float*)d_in[6];
    const float* q_w       = (const float*)d_in[7];
    const float* q_b       = (const float*)d_in[8];
    const float* k_w       = (const float*)d_in[9];
    const float* k_b       = (const float*)d_in[10];
    const float* ow        = (const float*)d_in[11];
    const float* ob        = (const float*)d_in[12];
    const float* w1        = (const float*)d_in[13];
    const float* b1        = (const float*)d_in[14];
    const float* w2        = (const float*)d_in[15];
    const float* b2        = (const float*)d_in[16];
    float* out = (float*)d_out;

    cudaFuncSetAttribute(decoder_kernel,
                         cudaFuncAttributeMaxDynamicSharedMemorySize, DYN_SMEM);

    attn_kernel<<<dim3(2, 64), 768>>>(timesteps, X, Mm, te_w, te_b, ow,
                                      query, q_w, q_b, k_w, k_b, ob);
    decoder_kernel<<<64, 512, DYN_SMEM>>>(y_ts, w1, b1, w2, b2, out);
}

// round 10
// speedup vs baseline: 1.6160x; 1.0903x over previous
#include <cuda_runtime.h>
#include <math.h>

#define Bk   64
#define Tk   512
#define Dd   96
#define TYk  512
#define Ek   128
#define Pk   2
#define Lk   64
#define HIDk 128

typedef unsigned long long u64;

// ---------------- f32x2 packed math helpers (sm_103a) ----------------------
__device__ __forceinline__ u64 ffma2(u64 a, u64 b, u64 c) {
    u64 d;
    asm("fma.rn.f32x2 %0, %1, %2, %3;" : "=l"(d) : "l"(a), "l"(b), "l"(c));
    return d;
}
__device__ __forceinline__ u64 pack2(float lo, float hi) {
    u64 d; asm("mov.b64 %0, {%1, %2};" : "=l"(d) : "f"(lo), "f"(hi)); return d;
}
__device__ __forceinline__ float2 unpack2(u64 v) {
    float2 r; asm("mov.b64 {%0, %1}, %2;" : "=f"(r.x), "=f"(r.y) : "l"(v)); return r;
}

// Scratch -------------------------------------------------------------------
__device__ float g_coeffs[2][64 * 128];   // per feature-half partial coeffs

// ---------------------------------------------------------------------------
// Kernel 1: attention, feature-split. grid = (2 f-halves, 64 b) x 768 thr.
// (unchanged)
// ---------------------------------------------------------------------------
__global__ __launch_bounds__(768) void attn_kernel(
    const float* __restrict__ timesteps, const float* __restrict__ X,
    const float* __restrict__ Mm,        const float* __restrict__ te_w,
    const float* __restrict__ te_b,      const float* __restrict__ ow,
    const float* __restrict__ query,     const float* __restrict__ q_w,
    const float* __restrict__ q_b,       const float* __restrict__ k_w,
    const float* __restrict__ k_b,       const float* __restrict__ ob)
{
    __shared__ __align__(16) float s_vt[128][8];
    __shared__ __align__(16) float s_et[512][8];
    __shared__ __align__(16) float s_buf[4][768];
    __shared__ float s_xa[8 * 48];
    __shared__ float s_den[8 * 48];
    __shared__ float s_cl[12][64];
    __shared__ float s_max[8];
    __shared__ float s_c[8];

    int fh = blockIdx.x;
    int b  = blockIdx.y;
    int tid = threadIdx.x;

    float* s_q  = &s_buf[0][0];
    float* s_qp = &s_buf[0][256];
    if (tid < 256) s_q[tid] = query[tid];
    {
        int rg = tid >> 6;
        int l = tid & 63;
        float a = 0.f;
        #pragma unroll 4
        for (int r = rg; r < 192; r += 12) {
            int h = r / 48, jj = r - h * 48;
            a += ow[(h * 192 + 96 + fh * 48 + jj) * 64 + l];
        }
        s_cl[rg][l] = a;
    }
    __syncthreads();
    if (tid < 256) {
        int p = tid >> 7, e = tid & 127;
        float acc = q_b[e];
        #pragma unroll 8
        for (int i = 0; i < 128; ++i)
            acc = fmaf(s_q[p * 128 + i], q_w[i * 128 + e], acc);
        s_qp[tid] = acc;
    }
    __syncthreads();
    for (int idx = tid; idx < 1024; idx += 768) {
        int hp = idx >> 7, ein = idx & 127;
        int h = hp >> 1, p = hp & 1;
        const float4* kr = (const float4*)(k_w + ein * 128 + h * 32);
        const float*  qp = &s_qp[p * 128 + h * 32];
        float acc = 0.f;
        #pragma unroll
        for (int d4 = 0; d4 < 8; ++d4) {
            float4 kv = __ldg(&kr[d4]);
            acc += qp[d4 * 4] * kv.x + qp[d4 * 4 + 1] * kv.y
                 + qp[d4 * 4 + 2] * kv.z + qp[d4 * 4 + 3] * kv.w;
        }
        s_vt[ein][hp] = acc;
    }
    if (tid < 8) {
        int h = tid >> 1, p = tid & 1;
        float acc = 0.f;
        #pragma unroll
        for (int d = 0; d < 32; ++d)
            acc = fmaf(s_qp[p * 128 + h * 32 + d], k_b[h * 32 + d], acc);
        s_c[tid] = acc;
    }
    __syncthreads();

    if (tid < 512) {
        float ts = timesteps[b * Tk + tid];
        u64 acc2[4];
        #pragma unroll
        for (int q = 0; q < 4; ++q) acc2[q] = pack2(s_c[2 * q], s_c[2 * q + 1]);
        const float4* w4p = (const float4*)te_w;
        const float4* b4p = (const float4*)te_b;
        #pragma unroll 4
        for (int e4 = 0; e4 < 32; ++e4) {
            float4 w4 = __ldg(&w4p[e4]);
            float4 b4 = __ldg(&b4p[e4]);
            float em[4];
            em[0] = __sinf(fmaf(ts, w4.x, b4.x));
            em[1] = fmaf(ts, w4.y, b4.y);
            em[2] = fmaf(ts, w4.z, b4.z);
            em[3] = fmaf(ts, w4.w, b4.w);
            #pragma unroll
            for (int j = 0; j < 4; ++j) {
                u64 emd = pack2(em[j], em[j]);
                ulonglong2 va = *(const ulonglong2*)&s_vt[e4 * 4 + j][0];
                ulonglong2 vb = *(const ulonglong2*)&s_vt[e4 * 4 + j][4];
                acc2[0] = ffma2(emd, va.x, acc2[0]);
                acc2[1] = ffma2(emd, va.y, acc2[1]);
                acc2[2] = ffma2(emd, vb.x, acc2[2]);
                acc2[3] = ffma2(emd, vb.y, acc2[3]);
            }
        }
        const float scale = 0.17677669529663687f;
        float2 a0 = unpack2(acc2[0]), a1 = unpack2(acc2[1]);
        float2 a2 = unpack2(acc2[2]), a3 = unpack2(acc2[3]);
        *(float4*)&s_et[tid][0] = make_float4(a0.x * scale, a0.y * scale, a1.x * scale, a1.y * scale);
        *(float4*)&s_et[tid][4] = make_float4(a2.x * scale, a2.y * scale, a3.x * scale, a3.y * scale);
    }
    __syncthreads();

    int warp = tid >> 5, lane = tid & 31;
    if (warp < 8) {
        float m = -1e30f;
        for (int t = lane; t < 512; t += 32) m = fmaxf(m, s_et[t][warp]);
        #pragma unroll
        for (int o = 16; o; o >>= 1) m = fmaxf(m, __shfl_xor_sync(0xffffffffu, m, o));
        if (lane == 0) s_max[warp] = m;
    }
    __syncthreads();
    for (int idx = tid; idx < 8 * 512; idx += 768) {
        int t = idx >> 3, hp = idx & 7;
        s_et[t][hp] = __expf(s_et[t][hp] - s_max[hp]);
    }
    __syncthreads();

    int tsub = tid / 24, f2l = tid - tsub * 24;
    u64 num[2][4], den[2][4];
    #pragma unroll
    for (int fs = 0; fs < 2; ++fs)
        #pragma unroll
        for (int q = 0; q < 4; ++q) { num[fs][q] = 0ull; den[fs][q] = 0ull; }
    {
        const float2* X2 = (const float2*)(X + (size_t)b * Tk * Dd);
        const float2* M2 = (const float2*)(Mm + (size_t)b * Tk * Dd);
        int fb = fh * 24;
        #pragma unroll 4
        for (int q = 0; q < 16; ++q) {
            int t = q * 32 + tsub;
            float2 x2 = __ldg(&X2[t * 48 + fb + f2l]);
            float2 m2 = __ldg(&M2[t * 48 + fb + f2l]);
            ulonglong2 e01 = *(const ulonglong2*)&s_et[t][0];
            ulonglong2 e23 = *(const ulonglong2*)&s_et[t][4];
            u64 m0  = pack2(m2.x, m2.x);
            u64 m1  = pack2(m2.y, m2.y);
            float xma = m2.x * x2.x, xmb = m2.y * x2.y;
            u64 xm0 = pack2(xma, xma);
            u64 xm1 = pack2(xmb, xmb);
            den[0][0] = ffma2(e01.x, m0, den[0][0]);
            den[0][1] = ffma2(e01.y, m0, den[0][1]);
            den[0][2] = ffma2(e23.x, m0, den[0][2]);
            den[0][3] = ffma2(e23.y, m0, den[0][3]);
            num[0][0] = ffma2(e01.x, xm0, num[0][0]);
            num[0][1] = ffma2(e01.y, xm0, num[0][1]);
            num[0][2] = ffma2(e23.x, xm0, num[0][2]);
            num[0][3] = ffma2(e23.y, xm0, num[0][3]);
            den[1][0] = ffma2(e01.x, m1, den[1][0]);
            den[1][1] = ffma2(e01.y, m1, den[1][1]);
            den[1][2] = ffma2(e23.x, m1, den[1][2]);
            den[1][3] = ffma2(e23.y, m1, den[1][3]);
            num[1][0] = ffma2(e01.x, xm1, num[1][0]);
            num[1][1] = ffma2(e01.y, xm1, num[1][1]);
            num[1][2] = ffma2(e23.x, xm1, num[1][2]);
            num[1][3] = ffma2(e23.y, xm1, num[1][3]);
        }
    }
    __syncthreads();

    float r_acc = 0.f;
    #pragma unroll
    for (int g = 0; g < 8; ++g) {
        if ((tsub >> 2) == g) {
            int gl = tsub & 3;
            #pragma unroll
            for (int fs = 0; fs < 2; ++fs) {
                int fl = 2 * f2l + fs;
                #pragma unroll
                for (int qq = 0; qq < 4; ++qq) {
                    float2 vn = unpack2(num[fs][qq]);
                    s_buf[gl][(2 * qq) * 48 + fl]           = vn.x;
                    s_buf[gl][(2 * qq + 1) * 48 + fl]       = vn.y;
                    float2 vd = unpack2(den[fs][qq]);
                    s_buf[gl][384 + (2 * qq) * 48 + fl]     = vd.x;
                    s_buf[gl][384 + (2 * qq + 1) * 48 + fl] = vd.y;
                }
            }
        }
        __syncthreads();
        r_acc += s_buf[0][tid] + s_buf[1][tid] + s_buf[2][tid] + s_buf[3][tid];
        __syncthreads();
    }
    if (tid >= 384) s_den[tid - 384] = r_acc;
    __syncthreads();
    if (tid < 384) s_xa[tid] = r_acc / s_den[tid];
    __syncthreads();

    float* s_scr = (float*)s_et;
    {
        int outIdx = tid & 127;
        int seg = tid >> 7;
        int p = outIdx >> 6, l = outIdx & 63;
        float acc = 0.f;
        #pragma unroll 4
        for (int r = seg * 32; r < seg * 32 + 32; ++r) {
            int h = r / 48, fl = r - h * 48;
            acc = fmaf(s_xa[(h * 2 + p) * 48 + fl],
                       ow[(h * 192 + fh * 48 + fl) * 64 + l], acc);
        }
        s_scr[tid] = acc;
    }
    __syncthreads();
    if (tid < 128) {
        int l = tid & 63;
        float acc = (fh == 0) ? ob[l] : 0.f;
        #pragma unroll
        for (int g = 0; g < 12; ++g) acc += s_cl[g][l];
        #pragma unroll
        for (int seg = 0; seg < 6; ++seg) acc += s_scr[seg * 128 + tid];
        g_coeffs[fh][b * 128 + tid] = acc;
    }
}

// ---------------------------------------------------------------------------
// Kernel 2: interval-classified decoder. 64 blocks x 512 threads, 6 syncs.
//   h_i(y) = A_i + y*B_i is linear; over [ymin,ymax] each unit is either
//   always-active (positive at both endpoints), never-active, or crossing.
//   Base C0/C1 from always-active set; crossing units (expected 0) patched
//   per-y in the eval loop.
// ---------------------------------------------------------------------------
__global__ __launch_bounds__(512) void decoder_kernel(
    const float* __restrict__ y_ts, const float* __restrict__ w1,
    const float* __restrict__ b1,   const float* __restrict__ w2,
    const float* __restrict__ b2,   float* __restrict__ out)
{
    __shared__ float sc0[64], sc1[64];
    __shared__ float sA[128], sB[128];        // masked (0 unless always-active)
    __shared__ float pA[4][128], pB[4][128];
    __shared__ float C0p[4][96], C1p[4][96];
    __shared__ float C0[96], C1[96];
    __shared__ float sy[512];
    __shared__ float redmin[16], redmax[16];
    __shared__ float s_ymin, s_ymax;
    __shared__ float crA[128], crB[128];
    __shared__ int   crI[128];
    __shared__ int   s_ncross;

    int b = blockIdx.x;
    int tid = threadIdx.x;
    int lane = tid & 31, warp = tid >> 5;

    // ---- Phase 1: loads + per-warp y min/max ----
    if (tid < 64) {
        sc0[tid] = g_coeffs[0][b * 128 + tid] + g_coeffs[1][b * 128 + tid];
    } else if (tid < 128) {
        int l = tid - 64;
        sc1[l] = g_coeffs[0][b * 128 + 64 + l] + g_coeffs[1][b * 128 + 64 + l];
    }
    if (tid == 0) s_ncross = 0;
    float yv = __ldg(&y_ts[(size_t)b * TYk + tid]);
    sy[tid] = yv;
    {
        float mn = yv, mx = yv;
        #pragma unroll
        for (int o = 16; o; o >>= 1) {
            mn = fminf(mn, __shfl_xor_sync(0xffffffffu, mn, o));
            mx = fmaxf(mx, __shfl_xor_sync(0xffffffffu, mx, o));
        }
        if (lane == 0) { redmin[warp] = mn; redmax[warp] = mx; }
    }
    __syncthreads();

    // ---- Phase 2: A/B split-K partials; one thread folds y extrema ----
    {
        int g = tid >> 7, i = tid & 127;
        float a = 0.f, bb = 0.f;
        #pragma unroll
        for (int l = g * 16; l < g * 16 + 16; ++l) {
            float w = __ldg(&w1[l * 128 + i]);
            a  = fmaf(sc0[l], w, a);
            bb = fmaf(sc1[l], w, bb);
        }
        pA[g][i] = a; pB[g][i] = bb;
    }
    if (tid == 0) {
        float mn = redmin[0], mx = redmax[0];
        #pragma unroll
        for (int wv = 1; wv < 16; ++wv) {
            mn = fminf(mn, redmin[wv]);
            mx = fmaxf(mx, redmax[wv]);
        }
        s_ymin = mn; s_ymax = mx;
    }
    __syncthreads();

    // ---- Phase 3: classify units ----
    if (tid < 128) {
        int i = tid;
        float a  = b1[i] + pA[0][i] + pA[1][i] + pA[2][i] + pA[3][i];
        float bb = pB[0][i] + pB[1][i] + pB[2][i] + pB[3][i];
        float h0 = fmaf(s_ymin, bb, a);
        float h1 = fmaf(s_ymax, bb, a);
        bool a0 = h0 > 0.f, a1 = h1 > 0.f;
        bool full = a0 && a1;
        sA[i] = full ? a  : 0.f;
        sB[i] = full ? bb : 0.f;
        if (a0 != a1) {
            int slot = atomicAdd(&s_ncross, 1);
            crA[slot] = a; crB[slot] = bb; crI[slot] = i;
        }
    }
    __syncthreads();

    // ---- Phase 4: base C0/C1 partials (384 threads, direct LDG of w2) ----
    if (tid < 384) {
        int g = tid / 96, j = tid - g * 96;
        float c0 = 0.f, c1 = 0.f;
        #pragma unroll 8
        for (int i = g * 32; i < g * 32 + 32; ++i) {
            float w = __ldg(&w2[i * 96 + j]);
            c0 = fmaf(sA[i], w, c0);
            c1 = fmaf(sB[i], w, c1);
        }
        C0p[g][j] = c0; C1p[g][j] = c1;
    }
    __syncthreads();

    // ---- Phase 5: fold base partials ----
    if (tid < 96) {
        C0[tid] = C0p[0][tid] + C0p[1][tid] + C0p[2][tid] + C0p[3][tid];
        C1[tid] = C1p[0][tid] + C1p[1][tid] + C1p[2][tid] + C1p[3][tid];
    }
    __syncthreads();

    // ---- Phase 6: eval. thread = (yg 0..63, jg 0..7 -> 12 j), 8 rounds ----
    int yg = tid >> 3, jg = tid & 7;
    int j0 = jg * 12;
    int ncross = s_ncross;
    float c0r[12], c1r[12], b2v[12];
    #pragma unroll
    for (int u = 0; u < 12; ++u) {
        c0r[u] = C0[j0 + u];
        c1r[u] = C1[j0 + u];
        b2v[u] = b2[j0 + u];
    }

    #pragma unroll 2
    for (int r = 0; r < 8; ++r) {
        int ty = r * 64 + yg;
        float y = sy[ty];
        float ov[12];
        #pragma unroll
        for (int u = 0; u < 12; ++u)
            ov[u] = fmaf(y, c1r[u], c0r[u]) + b2v[u];
        for (int k = 0; k < ncross; ++k) {        // uniform trip count (usually 0)
            float h = fmaf(y, crB[k], crA[k]);
            if (h > 0.f) {
                const float* wr = w2 + crI[k] * 96 + j0;
                #pragma unroll
                for (int u = 0; u < 12; ++u)
                    ov[u] = fmaf(h, __ldg(&wr[u]), ov[u]);
            }
        }
        float* o = out + ((size_t)b * TYk + ty) * Dd + j0;
        #pragma unroll
        for (int u = 0; u < 12; u += 2)
            *(float2*)&o[u] = make_float2(ov[u], ov[u + 1]);
    }
}

// ---------------------------------------------------------------------------
extern "C" void kernel_launch(void* const* d_in, const int* in_sizes, int n_in,
                              void* d_out, int out_size)
{
    const float* timesteps = (const float*)d_in[0];
    const float* X         = (const float*)d_in[1];
    const float* Mm        = (const float*)d_in[2];
    const float* y_ts      = (const float*)d_in[3];
    const float* te_w      = (const float*)d_in[4];
    const float* te_b      = (const float*)d_in[5];
    const float* query     = (const float*)d_in[6];
    const float* q_w       = (const float*)d_in[7];
    const float* q_b       = (const float*)d_in[8];
    const float* k_w       = (const float*)d_in[9];
    const float* k_b       = (const float*)d_in[10];
    const float* ow        = (const float*)d_in[11];
    const float* ob        = (const float*)d_in[12];
    const float* w1        = (const float*)d_in[13];
    const float* b1        = (const float*)d_in[14];
    const float* w2        = (const float*)d_in[15];
    const float* b2        = (const float*)d_in[16];
    float* out = (float*)d_out;

    attn_kernel<<<dim3(2, 64), 768>>>(timesteps, X, Mm, te_w, te_b, ow,
                                      query, q_w, q_b, k_w, k_b, ob);
    decoder_kernel<<<64, 512>>>(y_ts, w1, b1, w2, b2, out);
}

// round 12
// speedup vs baseline: 1.6273x; 1.0070x over previous
#include <cuda_runtime.h>
#include <math.h>

#define Bk   64
#define Tk   512
#define Dd   96
#define TYk  512

typedef unsigned long long u64;

__device__ __forceinline__ u64 ffma2(u64 a, u64 b, u64 c) {
    u64 d;
    asm("fma.rn.f32x2 %0, %1, %2, %3;" : "=l"(d) : "l"(a), "l"(b), "l"(c));
    return d;
}
__device__ __forceinline__ u64 pack2(float lo, float hi) {
    u64 d; asm("mov.b64 %0, {%1, %2};" : "=l"(d) : "f"(lo), "f"(hi)); return d;
}
__device__ __forceinline__ float2 unpack2(u64 v) {
    float2 r; asm("mov.b64 {%0, %1}, %2;" : "=f"(r.x), "=f"(r.y) : "l"(v)); return r;
}

// Scratch -------------------------------------------------------------------
__device__ float g_coeffs1[64 * 128];   // fh=1 partial coeffs
__device__ int   g_flag[64];            // zero-initialized; reset by consumer

#define RP 385                          // reduction row pitch (bank-safe)
#define DYN_FLOATS (2 * 32 * RP)        // 24640 floats (>= 20480 for w1+w2)
#define DYN_SMEM   (DYN_FLOATS * 4)

// ---------------------------------------------------------------------------
// Fused kernel. grid = (2 f-halves, 64 b) x 768 threads.
//   fh=1: attention half -> coeffs to global + flag, exit.
//   fh=0: attention half -> keep in smem; prefetch w1/w2 to smem; wait; decode.
// ---------------------------------------------------------------------------
__global__ __launch_bounds__(768) void fused_kernel(
    const float* __restrict__ timesteps, const float* __restrict__ X,
    const float* __restrict__ Mm,        const float* __restrict__ te_w,
    const float* __restrict__ te_b,      const float* __restrict__ ow,
    const float* __restrict__ query,     const float* __restrict__ q_w,
    const float* __restrict__ q_b,       const float* __restrict__ k_w,
    const float* __restrict__ k_b,       const float* __restrict__ ob,
    const float* __restrict__ y_ts,      const float* __restrict__ w1,
    const float* __restrict__ b1,        const float* __restrict__ w2,
    const float* __restrict__ b2,        float* __restrict__ out)
{
    extern __shared__ __align__(16) float dyn[];   // reduction scratch, then w1s|w2s

    // ---- attention statics ----
    __shared__ __align__(16) float s_vt[128][8];
    __shared__ __align__(16) float s_et[512][8];
    __shared__ float s_qbuf[512];
    __shared__ float s_xa[8 * 48];
    __shared__ float s_den[8 * 48];
    __shared__ float s_cl[12][64];
    __shared__ float s_max[8];
    __shared__ float s_c[8];
    // ---- decoder statics ----
    __shared__ float s_co[128], s_co1[128];
    __shared__ float sc0[64], sc1[64];
    __shared__ float sA[128], sB[128];
    __shared__ float pA[4][128], pB[4][128];
    __shared__ float C0p[4][96], C1p[4][96];
    __shared__ float C0[96], C1[96];
    __shared__ float sy[512];
    __shared__ float redmin[16], redmax[16];
    __shared__ float s_ymin, s_ymax;
    __shared__ float crA[128], crB[128];
    __shared__ int   crI[128];
    __shared__ int   s_ncross;

    int fh = blockIdx.x;
    int b  = blockIdx.y;
    int tid = threadIdx.x;
    int lane = tid & 31, warp = tid >> 5;

    // ================= Phase P: per-block precompute =======================
    float* s_q  = &s_qbuf[0];
    float* s_qp = &s_qbuf[256];
    if (tid < 256) s_q[tid] = query[tid];
    {
        int rg = tid >> 6;
        int l = tid & 63;
        float a = 0.f;
        #pragma unroll 4
        for (int r = rg; r < 192; r += 12) {
            int h = r / 48, jj = r - h * 48;
            a += ow[(h * 192 + 96 + fh * 48 + jj) * 64 + l];
        }
        s_cl[rg][l] = a;
    }
    __syncthreads();
    if (tid < 256) {
        int p = tid >> 7, e = tid & 127;
        float acc = q_b[e];
        #pragma unroll 8
        for (int i = 0; i < 128; ++i)
            acc = fmaf(s_q[p * 128 + i], q_w[i * 128 + e], acc);
        s_qp[tid] = acc;
    }
    __syncthreads();
    for (int idx = tid; idx < 1024; idx += 768) {
        int hp = idx >> 7, ein = idx & 127;
        int h = hp >> 1, p = hp & 1;
        const float4* kr = (const float4*)(k_w + ein * 128 + h * 32);
        const float*  qp = &s_qp[p * 128 + h * 32];
        float acc = 0.f;
        #pragma unroll
        for (int d4 = 0; d4 < 8; ++d4) {
            float4 kv = __ldg(&kr[d4]);
            acc += qp[d4 * 4] * kv.x + qp[d4 * 4 + 1] * kv.y
                 + qp[d4 * 4 + 2] * kv.z + qp[d4 * 4 + 3] * kv.w;
        }
        s_vt[ein][hp] = acc;
    }
    if (tid < 8) {
        int h = tid >> 1, p = tid & 1;
        float acc = 0.f;
        #pragma unroll
        for (int d = 0; d < 32; ++d)
            acc = fmaf(s_qp[p * 128 + h * 32 + d], k_b[h * 32 + d], acc);
        s_c[tid] = acc;
    }
    __syncthreads();

    // ================= Phase A: scores =====================================
    if (tid < 512) {
        float ts = timesteps[b * Tk + tid];
        u64 acc2[4];
        #pragma unroll
        for (int q = 0; q < 4; ++q) acc2[q] = pack2(s_c[2 * q], s_c[2 * q + 1]);
        const float4* w4p = (const float4*)te_w;
        const float4* b4p = (const float4*)te_b;
        #pragma unroll 4
        for (int e4 = 0; e4 < 32; ++e4) {
            float4 w4 = __ldg(&w4p[e4]);
            float4 b4 = __ldg(&b4p[e4]);
            float em[4];
            em[0] = __sinf(fmaf(ts, w4.x, b4.x));
            em[1] = fmaf(ts, w4.y, b4.y);
            em[2] = fmaf(ts, w4.z, b4.z);
            em[3] = fmaf(ts, w4.w, b4.w);
            #pragma unroll
            for (int j = 0; j < 4; ++j) {
                u64 emd = pack2(em[j], em[j]);
                ulonglong2 va = *(const ulonglong2*)&s_vt[e4 * 4 + j][0];
                ulonglong2 vb = *(const ulonglong2*)&s_vt[e4 * 4 + j][4];
                acc2[0] = ffma2(emd, va.x, acc2[0]);
                acc2[1] = ffma2(emd, va.y, acc2[1]);
                acc2[2] = ffma2(emd, vb.x, acc2[2]);
                acc2[3] = ffma2(emd, vb.y, acc2[3]);
            }
        }
        const float scale = 0.17677669529663687f;
        float2 a0 = unpack2(acc2[0]), a1 = unpack2(acc2[1]);
        float2 a2 = unpack2(acc2[2]), a3 = unpack2(acc2[3]);
        *(float4*)&s_et[tid][0] = make_float4(a0.x * scale, a0.y * scale, a1.x * scale, a1.y * scale);
        *(float4*)&s_et[tid][4] = make_float4(a2.x * scale, a2.y * scale, a3.x * scale, a3.y * scale);
    }
    __syncthreads();

    // ================= Phase B: per-hp max, exp ============================
    if (warp < 8) {
        float m = -1e30f;
        for (int t = lane; t < 512; t += 32) m = fmaxf(m, s_et[t][warp]);
        #pragma unroll
        for (int o = 16; o; o >>= 1) m = fmaxf(m, __shfl_xor_sync(0xffffffffu, m, o));
        if (lane == 0) s_max[warp] = m;
    }
    __syncthreads();
    for (int idx = tid; idx < 8 * 512; idx += 768) {
        int t = idx >> 3, hp = idx & 7;
        s_et[t][hp] = __expf(s_et[t][hp] - s_max[hp]);
    }
    __syncthreads();

    // ================= Phase C: direct-LDG masked accumulation =============
    int tsub = tid / 24, f2l = tid - tsub * 24;
    u64 num[2][4], den[2][4];
    #pragma unroll
    for (int fs = 0; fs < 2; ++fs)
        #pragma unroll
        for (int q = 0; q < 4; ++q) { num[fs][q] = 0ull; den[fs][q] = 0ull; }
    {
        const float2* X2 = (const float2*)(X + (size_t)b * Tk * Dd);
        const float2* M2 = (const float2*)(Mm + (size_t)b * Tk * Dd);
        int fb = fh * 24;
        #pragma unroll 4
        for (int q = 0; q < 16; ++q) {
            int t = q * 32 + tsub;
            float2 x2 = __ldg(&X2[t * 48 + fb + f2l]);
            float2 m2 = __ldg(&M2[t * 48 + fb + f2l]);
            ulonglong2 e01 = *(const ulonglong2*)&s_et[t][0];
            ulonglong2 e23 = *(const ulonglong2*)&s_et[t][4];
            u64 m0  = pack2(m2.x, m2.x);
            u64 m1  = pack2(m2.y, m2.y);
            float xma = m2.x * x2.x, xmb = m2.y * x2.y;
            u64 xm0 = pack2(xma, xma);
            u64 xm1 = pack2(xmb, xmb);
            den[0][0] = ffma2(e01.x, m0, den[0][0]);
            den[0][1] = ffma2(e01.y, m0, den[0][1]);
            den[0][2] = ffma2(e23.x, m0, den[0][2]);
            den[0][3] = ffma2(e23.y, m0, den[0][3]);
            num[0][0] = ffma2(e01.x, xm0, num[0][0]);
            num[0][1] = ffma2(e01.y, xm0, num[0][1]);
            num[0][2] = ffma2(e23.x, xm0, num[0][2]);
            num[0][3] = ffma2(e23.y, xm0, num[0][3]);
            den[1][0] = ffma2(e01.x, m1, den[1][0]);
            den[1][1] = ffma2(e01.y, m1, den[1][1]);
            den[1][2] = ffma2(e23.x, m1, den[1][2]);
            den[1][3] = ffma2(e23.y, m1, den[1][3]);
            num[1][0] = ffma2(e01.x, xm1, num[1][0]);
            num[1][1] = ffma2(e01.y, xm1, num[1][1]);
            num[1][2] = ffma2(e23.x, xm1, num[1][2]);
            num[1][3] = ffma2(e23.y, xm1, num[1][3]);
        }
    }
    __syncthreads();   // s_qbuf retired; dyn scratch about to be written

    // ---- single-pass reduction through dynamic smem (2 barriers) ----
    float* s_rn = dyn;               // [32][RP]
    float* s_rd = dyn + 32 * RP;     // [32][RP]
    #pragma unroll
    for (int fs = 0; fs < 2; ++fs) {
        int fl = 2 * f2l + fs;
        #pragma unroll
        for (int qq = 0; qq < 4; ++qq) {
            float2 vn = unpack2(num[fs][qq]);
            s_rn[tsub * RP + (2 * qq) * 48 + fl]     = vn.x;
            s_rn[tsub * RP + (2 * qq + 1) * 48 + fl] = vn.y;
            float2 vd = unpack2(den[fs][qq]);
            s_rd[tsub * RP + (2 * qq) * 48 + fl]     = vd.x;
            s_rd[tsub * RP + (2 * qq + 1) * 48 + fl] = vd.y;
        }
    }
    __syncthreads();
    {
        int slot = (tid < 384) ? tid : tid - 384;
        const float* base = (tid < 384) ? s_rn : s_rd;
        float a0 = 0.f, a1 = 0.f, a2 = 0.f, a3 = 0.f;
        #pragma unroll
        for (int r = 0; r < 32; r += 4) {
            a0 += base[(r + 0) * RP + slot];
            a1 += base[(r + 1) * RP + slot];
            a2 += base[(r + 2) * RP + slot];
            a3 += base[(r + 3) * RP + slot];
        }
        float r_acc = (a0 + a1) + (a2 + a3);
        if (tid >= 384) s_den[slot] = r_acc;
        __syncthreads();
        if (tid < 384) s_xa[tid] = r_acc / s_den[tid];
    }
    __syncthreads();

    // ================= Phase D: partial coeffs =============================
    float* s_scr = (float*)s_et;
    {
        int outIdx = tid & 127;
        int seg = tid >> 7;
        int p = outIdx >> 6, l = outIdx & 63;
        float acc = 0.f;
        #pragma unroll 4
        for (int r = seg * 32; r < seg * 32 + 32; ++r) {
            int h = r / 48, fl = r - h * 48;
            acc = fmaf(s_xa[(h * 2 + p) * 48 + fl],
                       ow[(h * 192 + fh * 48 + fl) * 64 + l], acc);
        }
        s_scr[tid] = acc;
    }
    __syncthreads();
    float cv = 0.f;
    if (tid < 128) {
        int l = tid & 63;
        cv = (fh == 0) ? ob[l] : 0.f;
        #pragma unroll
        for (int g = 0; g < 12; ++g) cv += s_cl[g][l];
        #pragma unroll
        for (int seg = 0; seg < 6; ++seg) cv += s_scr[seg * 128 + tid];
    }

    // ================= Producer epilogue (fh == 1) =========================
    if (fh == 1) {
        if (tid < 128) g_coeffs1[b * 128 + tid] = cv;
        __threadfence();
        __syncthreads();
        if (tid == 0) atomicExch(&g_flag[b], 1);
        return;
    }

    // ================= Consumer: decoder ===================================
    if (tid < 128) s_co[tid] = cv;
    if (tid == 0) s_ncross = 0;
    // y + per-warp min/max (first 512 threads)
    if (tid < 512) {
        float yv = __ldg(&y_ts[(size_t)b * TYk + tid]);
        sy[tid] = yv;
        float mn = yv, mx = yv;
        #pragma unroll
        for (int o = 16; o; o >>= 1) {
            mn = fminf(mn, __shfl_xor_sync(0xffffffffu, mn, o));
            mx = fmaxf(mx, __shfl_xor_sync(0xffffffffu, mx, o));
        }
        if (lane == 0) { redmin[warp] = mn; redmax[warp] = mx; }
    }
    // prefetch w1|w2 into dyn (free after reduction): 2048 + 3072 float4
    float* w1s = dyn;                 // [64][128]
    float* w2s = dyn + 8192;          // [128][96]
    {
        const float4* src1 = (const float4*)w1;
        float4* dst1 = (float4*)w1s;
        for (int i = tid; i < 2048; i += 768) dst1[i] = __ldg(&src1[i]);
        const float4* src2 = (const float4*)w2;
        float4* dst2 = (float4*)w2s;
        for (int i = tid; i < 3072; i += 768) dst2[i] = __ldg(&src2[i]);
    }
    __syncthreads();
    if (tid == 0) {
        float mn = redmin[0], mx = redmax[0];
        #pragma unroll
        for (int wv = 1; wv < 16; ++wv) {
            mn = fminf(mn, redmin[wv]);
            mx = fmaxf(mx, redmax[wv]);
        }
        s_ymin = mn; s_ymax = mx;
        while (atomicAdd(&g_flag[b], 0) == 0) __nanosleep(64);
        __threadfence();
    }
    __syncthreads();
    if (tid < 128) s_co1[tid] = g_coeffs1[b * 128 + tid];
    __syncthreads();
    if (tid == 0) atomicExch(&g_flag[b], 0);
    if (tid < 64)       sc0[tid] = s_co[tid] + s_co1[tid];
    else if (tid < 128) sc1[tid - 64] = s_co[tid] + s_co1[tid];
    __syncthreads();

    // ---- A/B split-K from smem w1 ----
    if (tid < 512) {
        int g = tid >> 7, i = tid & 127;
        float a = 0.f, bb = 0.f;
        #pragma unroll
        for (int l = g * 16; l < g * 16 + 16; ++l) {
            float w = w1s[l * 128 + i];
            a  = fmaf(sc0[l], w, a);
            bb = fmaf(sc1[l], w, bb);
        }
        pA[g][i] = a; pB[g][i] = bb;
    }
    __syncthreads();
    // ---- classify units over [ymin, ymax] ----
    if (tid < 128) {
        int i = tid;
        float a  = b1[i] + pA[0][i] + pA[1][i] + pA[2][i] + pA[3][i];
        float bb = pB[0][i] + pB[1][i] + pB[2][i] + pB[3][i];
        float h0 = fmaf(s_ymin, bb, a);
        float h1 = fmaf(s_ymax, bb, a);
        bool a0 = h0 > 0.f, a1 = h1 > 0.f;
        bool full = a0 && a1;
        sA[i] = full ? a  : 0.f;
        sB[i] = full ? bb : 0.f;
        if (a0 != a1) {
            int slot = atomicAdd(&s_ncross, 1);
            crA[slot] = a; crB[slot] = bb; crI[slot] = i;
        }
    }
    __syncthreads();
    // ---- base C0/C1 partials from smem w2 ----
    if (tid < 384) {
        int g = tid / 96, j = tid - g * 96;
        float c0 = 0.f, c1 = 0.f;
        #pragma unroll 8
        for (int i = g * 32; i < g * 32 + 32; ++i) {
            float w = w2s[i * 96 + j];
            c0 = fmaf(sA[i], w, c0);
            c1 = fmaf(sB[i], w, c1);
        }
        C0p[g][j] = c0; C1p[g][j] = c1;
    }
    __syncthreads();
    if (tid < 96) {
        C0[tid] = C0p[0][tid] + C0p[1][tid] + C0p[2][tid] + C0p[3][tid];
        C1[tid] = C1p[0][tid] + C1p[1][tid] + C1p[2][tid] + C1p[3][tid];
    }
    __syncthreads();

    // ---- eval (first 512 threads): thread = (yg, jg -> 12 j), 8 rounds ----
    if (tid < 512) {
        int yg = tid >> 3, jg = tid & 7;
        int j0 = jg * 12;
        int ncross = s_ncross;
        float c0r[12], c1r[12], b2v[12];
        #pragma unroll
        for (int u = 0; u < 12; ++u) {
            c0r[u] = C0[j0 + u];
            c1r[u] = C1[j0 + u];
            b2v[u] = b2[j0 + u];
        }
        #pragma unroll 2
        for (int r = 0; r < 8; ++r) {
            int ty = r * 64 + yg;
            float y = sy[ty];
            float ov[12];
            #pragma unroll
            for (int u = 0; u < 12; ++u)
                ov[u] = fmaf(y, c1r[u], c0r[u]) + b2v[u];
            for (int k = 0; k < ncross; ++k) {     // usually 0 iterations
                float h = fmaf(y, crB[k], crA[k]);
                if (h > 0.f) {
                    const float* wr = w2s + crI[k] * 96 + j0;
                    #pragma unroll
                    for (int u = 0; u < 12; ++u)
                        ov[u] = fmaf(h, wr[u], ov[u]);
                }
            }
            float* o = out + ((size_t)b * TYk + ty) * Dd + j0;
            #pragma unroll
            for (int u = 0; u < 12; u += 2)
                *(float2*)&o[u] = make_float2(ov[u], ov[u + 1]);
        }
    }
}

// ---------------------------------------------------------------------------
extern "C" void kernel_launch(void* const* d_in, const int* in_sizes, int n_in,
                              void* d_out, int out_size)
{
    const float* timesteps = (const float*)d_in[0];
    const float* X         = (const float*)d_in[1];
    const float* Mm        = (const float*)d_in[2];
    const float* y_ts      = (const float*)d_in[3];
    const float* te_w      = (const float*)d_in[4];
    const float* te_b      = (const float*)d_in[5];
    const float* query     = (const float*)d_in[6];
    const float* q_w       = (const float*)d_in[7];
    const float* q_b       = (const float*)d_in[8];
    const float* k_w       = (const float*)d_in[9];
    const float* k_b       = (const float*)d_in[10];
    const float* ow        = (const float*)d_in[11];
    const float* ob        = (const float*)d_in[12];
    const float* w1        = (const float*)d_in[13];
    const float* b1        = (const float*)d_in[14];
    const float* w2        = (const float*)d_in[15];
    const float* b2        = (const float*)d_in[16];
    float* out = (float*)d_out;

    cudaFuncSetAttribute(fused_kernel,
                         cudaFuncAttributeMaxDynamicSharedMemorySize, DYN_SMEM);

    fused_kernel<<<dim3(2, 64), 768, DYN_SMEM>>>(
        timesteps, X, Mm, te_w, te_b, ow, query, q_w, q_b, k_w, k_b, ob,
        y_ts, w1, b1, w2, b2, out);
}

// round 16
// speedup vs baseline: 1.8919x; 1.1626x over previous
#include <cuda_runtime.h>
#include <math.h>

#define Bk   64
#define Tk   512
#define Dd   96
#define TYk  512

typedef unsigned long long u64;

__device__ __forceinline__ u64 ffma2(u64 a, u64 b, u64 c) {
    u64 d;
    asm("fma.rn.f32x2 %0, %1, %2, %3;" : "=l"(d) : "l"(a), "l"(b), "l"(c));
    return d;
}
__device__ __forceinline__ u64 pack2(float lo, float hi) {
    u64 d; asm("mov.b64 %0, {%1, %2};" : "=l"(d) : "f"(lo), "f"(hi)); return d;
}
__device__ __forceinline__ float2 unpack2(u64 v) {
    float2 r; asm("mov.b64 {%0, %1}, %2;" : "=f"(r.x), "=f"(r.y) : "l"(v)); return r;
}

// Scratch -------------------------------------------------------------------
__device__ float g_coeffs1[64 * 128];   // fh=1 partial coeffs
__device__ int   g_flag[64];            // zero-initialized; reset by consumer

#define RP 385                          // reduction row pitch (bank-safe)
#define DYN_FLOATS (2 * 32 * RP)
#define DYN_SMEM   (DYN_FLOATS * 4)

// ---------------------------------------------------------------------------
// Fused kernel. grid = (2 f-halves, 64 b) x 768 threads.
// ---------------------------------------------------------------------------
__global__ __launch_bounds__(768) void fused_kernel(
    const float* __restrict__ timesteps, const float* __restrict__ X,
    const float* __restrict__ Mm,        const float* __restrict__ te_w,
    const float* __restrict__ te_b,      const float* __restrict__ ow,
    const float* __restrict__ query,     const float* __restrict__ q_w,
    const float* __restrict__ q_b,       const float* __restrict__ k_w,
    const float* __restrict__ k_b,       const float* __restrict__ ob,
    const float* __restrict__ y_ts,      const float* __restrict__ w1,
    const float* __restrict__ b1,        const float* __restrict__ w2,
    const float* __restrict__ b2,        float* __restrict__ out)
{
    extern __shared__ __align__(16) float dyn[];   // reduction scratch

    // ---- attention statics ----
    __shared__ __align__(16) float s_vt[128][8];
    __shared__ __align__(16) float s_et[512][8];
    __shared__ float s_qbuf[512];
    __shared__ float s_xa[8 * 48];
    __shared__ float s_den[8 * 48];
    __shared__ float s_cl[12][64];
    __shared__ float s_c[8];
    __shared__ float sP[8], sQc[8];     // folded linear part of emb
    // ---- decoder statics ----
    __shared__ float s_co[128], s_co1[128];
    __shared__ float sc0[64], sc1[64];
    __shared__ float sA[128], sB[128];
    __shared__ float pA[4][128], pB[4][128];
    __shared__ float C0p[4][96], C1p[4][96];
    __shared__ float C0[96], C1[96];
    __shared__ float sy[512];
    __shared__ float redmin[16], redmax[16];
    __shared__ float s_ymin, s_ymax;
    __shared__ float crA[128], crB[128];
    __shared__ int   crI[128];
    __shared__ int   s_ncross;

    int fh = blockIdx.x;
    int b  = blockIdx.y;
    int tid = threadIdx.x;
    int lane = tid & 31, warp = tid >> 5;

    // ================= Phase P: per-block precompute =======================
    float* s_q  = &s_qbuf[0];
    float* s_qp = &s_qbuf[256];
    if (tid < 256) s_q[tid] = query[tid];
    {
        int rg = tid >> 6;
        int l = tid & 63;
        float a = 0.f;
        #pragma unroll 4
        for (int r = rg; r < 192; r += 12) {
            int h = r / 48, jj = r - h * 48;
            a += ow[(h * 192 + 96 + fh * 48 + jj) * 64 + l];
        }
        s_cl[rg][l] = a;
    }
    __syncthreads();
    if (tid < 256) {
        int p = tid >> 7, e = tid & 127;
        float acc = q_b[e];
        #pragma unroll 8
        for (int i = 0; i < 128; ++i)
            acc = fmaf(s_q[p * 128 + i], q_w[i * 128 + e], acc);
        s_qp[tid] = acc;
    }
    __syncthreads();
    for (int idx = tid; idx < 1024; idx += 768) {
        int hp = idx >> 7, ein = idx & 127;
        int h = hp >> 1, p = hp & 1;
        const float4* kr = (const float4*)(k_w + ein * 128 + h * 32);
        const float*  qp = &s_qp[p * 128 + h * 32];
        float acc = 0.f;
        #pragma unroll
        for (int d4 = 0; d4 < 8; ++d4) {
            float4 kv = __ldg(&kr[d4]);
            acc += qp[d4 * 4] * kv.x + qp[d4 * 4 + 1] * kv.y
                 + qp[d4 * 4 + 2] * kv.z + qp[d4 * 4 + 3] * kv.w;
        }
        s_vt[ein][hp] = acc;
    }
    if (tid < 8) {
        int h = tid >> 1, p = tid & 1;
        float acc = 0.f;
        #pragma unroll
        for (int d = 0; d < 32; ++d)
            acc = fmaf(s_qp[p * 128 + h * 32 + d], k_b[h * 32 + d], acc);
        s_c[tid] = acc;
    }
    __syncthreads();

    // ---- fold linear emb lanes (e%4 != 0) into per-hp P, Q ----
    if (tid < 256) {
        int hp = tid >> 5, ln = tid & 31;   // one warp per hp
        float pPv = 0.f, pQv = 0.f;
        #pragma unroll
        for (int j = 1; j < 4; ++j) {
            int e = 4 * ln + j;
            float v = s_vt[e][hp];
            pPv = fmaf(v, __ldg(&te_w[e]), pPv);
            pQv = fmaf(v, __ldg(&te_b[e]), pQv);
        }
        #pragma unroll
        for (int o = 16; o; o >>= 1) {
            pPv += __shfl_xor_sync(0xffffffffu, pPv, o);
            pQv += __shfl_xor_sync(0xffffffffu, pQv, o);
        }
        if (ln == 0) { sP[hp] = pPv; sQc[hp] = pQv + s_c[hp]; }
    }
    __syncthreads();

    // ================= Phase A: scores -> exp (no max; values are small) ===
    if (tid < 512) {
        float ts = timesteps[b * Tk + tid];
        u64 acc2[4];
        #pragma unroll
        for (int q = 0; q < 4; ++q) {
            float b0 = fmaf(ts, sP[2 * q],     sQc[2 * q]);
            float b1v = fmaf(ts, sP[2 * q + 1], sQc[2 * q + 1]);
            acc2[q] = pack2(b0, b1v);
        }
        #pragma unroll 4
        for (int es = 0; es < 32; ++es) {
            int e = 4 * es;
            float sv = __sinf(fmaf(ts, __ldg(&te_w[e]), __ldg(&te_b[e])));
            u64 svd = pack2(sv, sv);
            ulonglong2 va = *(const ulonglong2*)&s_vt[e][0];
            ulonglong2 vb = *(const ulonglong2*)&s_vt[e][4];
            acc2[0] = ffma2(svd, va.x, acc2[0]);
            acc2[1] = ffma2(svd, va.y, acc2[1]);
            acc2[2] = ffma2(svd, vb.x, acc2[2]);
            acc2[3] = ffma2(svd, vb.y, acc2[3]);
        }
        const float scale = 0.17677669529663687f;  // 1/sqrt(32)
        float2 a0 = unpack2(acc2[0]), a1 = unpack2(acc2[1]);
        float2 a2 = unpack2(acc2[2]), a3 = unpack2(acc2[3]);
        *(float4*)&s_et[tid][0] = make_float4(
            __expf(a0.x * scale), __expf(a0.y * scale),
            __expf(a1.x * scale), __expf(a1.y * scale));
        *(float4*)&s_et[tid][4] = make_float4(
            __expf(a2.x * scale), __expf(a2.y * scale),
            __expf(a3.x * scale), __expf(a3.y * scale));
    }
    __syncthreads();

    // ================= Phase C: direct-LDG masked accumulation =============
    int tsub = tid / 24, f2l = tid - tsub * 24;
    u64 num[2][4], den[2][4];
    #pragma unroll
    for (int fs = 0; fs < 2; ++fs)
        #pragma unroll
        for (int q = 0; q < 4; ++q) { num[fs][q] = 0ull; den[fs][q] = 0ull; }
    {
        const float2* X2 = (const float2*)(X + (size_t)b * Tk * Dd);
        const float2* M2 = (const float2*)(Mm + (size_t)b * Tk * Dd);
        int fb = fh * 24;
        #pragma unroll 4
        for (int q = 0; q < 16; ++q) {
            int t = q * 32 + tsub;
            float2 x2 = __ldg(&X2[t * 48 + fb + f2l]);
            float2 m2 = __ldg(&M2[t * 48 + fb + f2l]);
            ulonglong2 e01 = *(const ulonglong2*)&s_et[t][0];
            ulonglong2 e23 = *(const ulonglong2*)&s_et[t][4];
            u64 m0  = pack2(m2.x, m2.x);
            u64 m1  = pack2(m2.y, m2.y);
            float xma = m2.x * x2.x, xmb = m2.y * x2.y;
            u64 xm0 = pack2(xma, xma);
            u64 xm1 = pack2(xmb, xmb);
            den[0][0] = ffma2(e01.x, m0, den[0][0]);
            den[0][1] = ffma2(e01.y, m0, den[0][1]);
            den[0][2] = ffma2(e23.x, m0, den[0][2]);
            den[0][3] = ffma2(e23.y, m0, den[0][3]);
            num[0][0] = ffma2(e01.x, xm0, num[0][0]);
            num[0][1] = ffma2(e01.y, xm0, num[0][1]);
            num[0][2] = ffma2(e23.x, xm0, num[0][2]);
            num[0][3] = ffma2(e23.y, xm0, num[0][3]);
            den[1][0] = ffma2(e01.x, m1, den[1][0]);
            den[1][1] = ffma2(e01.y, m1, den[1][1]);
            den[1][2] = ffma2(e23.x, m1, den[1][2]);
            den[1][3] = ffma2(e23.y, m1, den[1][3]);
            num[1][0] = ffma2(e01.x, xm1, num[1][0]);
            num[1][1] = ffma2(e01.y, xm1, num[1][1]);
            num[1][2] = ffma2(e23.x, xm1, num[1][2]);
            num[1][3] = ffma2(e23.y, xm1, num[1][3]);
        }
    }
    __syncthreads();

    // ---- single-pass reduction through dynamic smem (2 barriers) ----
    float* s_rn = dyn;               // [32][RP]
    float* s_rd = dyn + 32 * RP;     // [32][RP]
    #pragma unroll
    for (int fs = 0; fs < 2; ++fs) {
        int fl = 2 * f2l + fs;
        #pragma unroll
        for (int qq = 0; qq < 4; ++qq) {
            float2 vn = unpack2(num[fs][qq]);
            s_rn[tsub * RP + (2 * qq) * 48 + fl]     = vn.x;
            s_rn[tsub * RP + (2 * qq + 1) * 48 + fl] = vn.y;
            float2 vd = unpack2(den[fs][qq]);
            s_rd[tsub * RP + (2 * qq) * 48 + fl]     = vd.x;
            s_rd[tsub * RP + (2 * qq + 1) * 48 + fl] = vd.y;
        }
    }
    __syncthreads();
    {
        int slot = (tid < 384) ? tid : tid - 384;
        const float* base = (tid < 384) ? s_rn : s_rd;
        float a0 = 0.f, a1 = 0.f, a2 = 0.f, a3 = 0.f;
        #pragma unroll
        for (int r = 0; r < 32; r += 4) {
            a0 += base[(r + 0) * RP + slot];
            a1 += base[(r + 1) * RP + slot];
            a2 += base[(r + 2) * RP + slot];
            a3 += base[(r + 3) * RP + slot];
        }
        float r_acc = (a0 + a1) + (a2 + a3);
        if (tid >= 384) s_den[slot] = r_acc;
        __syncthreads();
        if (tid < 384) s_xa[tid] = r_acc / s_den[tid];
    }
    __syncthreads();

    // ================= Phase D: partial coeffs =============================
    float* s_scr = (float*)s_et;
    {
        int outIdx = tid & 127;
        int seg = tid >> 7;
        int p = outIdx >> 6, l = outIdx & 63;
        float acc = 0.f;
        #pragma unroll 4
        for (int r = seg * 32; r < seg * 32 + 32; ++r) {
            int h = r / 48, fl = r - h * 48;
            acc = fmaf(s_xa[(h * 2 + p) * 48 + fl],
                       ow[(h * 192 + fh * 48 + fl) * 64 + l], acc);
        }
        s_scr[tid] = acc;
    }
    __syncthreads();
    float cv = 0.f;
    if (tid < 128) {
        int l = tid & 63;
        cv = (fh == 0) ? ob[l] : 0.f;
        #pragma unroll
        for (int g = 0; g < 12; ++g) cv += s_cl[g][l];
        #pragma unroll
        for (int seg = 0; seg < 6; ++seg) cv += s_scr[seg * 128 + tid];
    }

    // ================= Producer epilogue (fh == 1) =========================
    if (fh == 1) {
        if (tid < 128) g_coeffs1[b * 128 + tid] = cv;
        __threadfence();
        __syncthreads();
        if (tid == 0) atomicExch(&g_flag[b], 1);
        return;
    }

    // ================= Consumer: decoder ===================================
    if (tid < 128) s_co[tid] = cv;
    if (tid == 0) s_ncross = 0;
    if (tid < 512) {
        float yv = __ldg(&y_ts[(size_t)b * TYk + tid]);
        sy[tid] = yv;
        float mn = yv, mx = yv;
        #pragma unroll
        for (int o = 16; o; o >>= 1) {
            mn = fminf(mn, __shfl_xor_sync(0xffffffffu, mn, o));
            mx = fmaxf(mx, __shfl_xor_sync(0xffffffffu, mx, o));
        }
        if (lane == 0) { redmin[warp] = mn; redmax[warp] = mx; }
    }
    __syncthreads();
    if (tid == 0) {
        float mn = redmin[0], mx = redmax[0];
        #pragma unroll
        for (int wv = 1; wv < 16; ++wv) {
            mn = fminf(mn, redmin[wv]);
            mx = fmaxf(mx, redmax[wv]);
        }
        s_ymin = mn; s_ymax = mx;
        while (atomicAdd(&g_flag[b], 0) == 0) __nanosleep(64);
        __threadfence();
    }
    __syncthreads();
    if (tid < 128) s_co1[tid] = g_coeffs1[b * 128 + tid];
    __syncthreads();
    if (tid == 0) atomicExch(&g_flag[b], 0);
    if (tid < 64)       sc0[tid] = s_co[tid] + s_co1[tid];
    else if (tid < 128) sc1[tid - 64] = s_co[tid] + s_co1[tid];
    __syncthreads();

    // ---- A/B split-K (direct LDG of w1) ----
    if (tid < 512) {
        int g = tid >> 7, i = tid & 127;
        float a = 0.f, bb = 0.f;
        #pragma unroll
        for (int l = g * 16; l < g * 16 + 16; ++l) {
            float w = __ldg(&w1[l * 128 + i]);
            a  = fmaf(sc0[l], w, a);
            bb = fmaf(sc1[l], w, bb);
        }
        pA[g][i] = a; pB[g][i] = bb;
    }
    __syncthreads();
    // ---- classify units over [ymin, ymax] ----
    if (tid < 128) {
        int i = tid;
        float a  = b1[i] + pA[0][i] + pA[1][i] + pA[2][i] + pA[3][i];
        float bb = pB[0][i] + pB[1][i] + pB[2][i] + pB[3][i];
        float h0 = fmaf(s_ymin, bb, a);
        float h1 = fmaf(s_ymax, bb, a);
        bool a0 = h0 > 0.f, a1 = h1 > 0.f;
        bool full = a0 && a1;
        sA[i] = full ? a  : 0.f;
        sB[i] = full ? bb : 0.f;
        if (a0 != a1) {
            int slot = atomicAdd(&s_ncross, 1);
            crA[slot] = a; crB[slot] = bb; crI[slot] = i;
        }
    }
    __syncthreads();
    // ---- base C0/C1 partials (direct LDG of w2) ----
    if (tid < 384) {
        int g = tid / 96, j = tid - g * 96;
        float c0 = 0.f, c1 = 0.f;
        #pragma unroll 8
        for (int i = g * 32; i < g * 32 + 32; ++i) {
            float w = __ldg(&w2[i * 96 + j]);
            c0 = fmaf(sA[i], w, c0);
            c1 = fmaf(sB[i], w, c1);
        }
        C0p[g][j] = c0; C1p[g][j] = c1;
    }
    __syncthreads();
    if (tid < 96) {
        C0[tid] = C0p[0][tid] + C0p[1][tid] + C0p[2][tid] + C0p[3][tid];
        C1[tid] = C1p[0][tid] + C1p[1][tid] + C1p[2][tid] + C1p[3][tid];
    }
    __syncthreads();

    // ---- eval (first 512 threads) ----
    if (tid < 512) {
        int yg = tid >> 3, jg = tid & 7;
        int j0 = jg * 12;
        int ncross = s_ncross;
        float c0r[12], c1r[12], b2v[12];
        #pragma unroll
        for (int u = 0; u < 12; ++u) {
            c0r[u] = C0[j0 + u];
            c1r[u] = C1[j0 + u];
            b2v[u] = b2[j0 + u];
        }
        #pragma unroll 2
        for (int r = 0; r < 8; ++r) {
            int ty = r * 64 + yg;
            float y = sy[ty];
            float ov[12];
            #pragma unroll
            for (int u = 0; u < 12; ++u)
                ov[u] = fmaf(y, c1r[u], c0r[u]) + b2v[u];
            for (int k = 0; k < ncross; ++k) {     // usually 0 iterations
                float h = fmaf(y, crB[k], crA[k]);
                if (h > 0.f) {
                    const float* wr = w2 + crI[k] * 96 + j0;
                    #pragma unroll
                    for (int u = 0; u < 12; ++u)
                        ov[u] = fmaf(h, __ldg(&wr[u]), ov[u]);
                }
            }
            float* o = out + ((size_t)b * TYk + ty) * Dd + j0;
            #pragma unroll
            for (int u = 0; u < 12; u += 2)
                *(float2*)&o[u] = make_float2(ov[u], ov[u + 1]);
        }
    }
}

// ---------------------------------------------------------------------------
extern "C" void kernel_launch(void* const* d_in, const int* in_sizes, int n_in,
                              void* d_out, int out_size)
{
    const float* timesteps = (const float*)d_in[0];
    const float* X         = (const float*)d_in[1];
    const float* Mm        = (const float*)d_in[2];
    const float* y_ts      = (const float*)d_in[3];
    const float* te_w      = (const float*)d_in[4];
    const float* te_b      = (const float*)d_in[5];
    const float* query     = (const float*)d_in[6];
    const float* q_w       = (const float*)d_in[7];
    const float* q_b       = (const float*)d_in[8];
    const float* k_w       = (const float*)d_in[9];
    const float* k_b       = (const float*)d_in[10];
    const float* ow        = (const float*)d_in[11];
    const float* ob        = (const float*)d_in[12];
    const float* w1        = (const float*)d_in[13];
    const float* b1        = (const float*)d_in[14];
    const float* w2        = (const float*)d_in[15];
    const float* b2        = (const float*)d_in[16];
    float* out = (float*)d_out;

    cudaFuncSetAttribute(fused_kernel,
                         cudaFuncAttributeMaxDynamicSharedMemorySize, DYN_SMEM);

    fused_kernel<<<dim3(2, 64), 768, DYN_SMEM>>>(
        timesteps, X, Mm, te_w, te_b, ow, query, q_w, q_b, k_w, k_b, ob,
        y_ts, w1, b1, w2, b2, out);
}